// round 3
// baseline (speedup 1.0000x reference)
#include <cuda_runtime.h>
#include <cuda_bf16.h>

// Problem constants (fixed by dataset): N=50000 nodes, E=1.6M edges, K=128 feat dim.
#define NODE_CAP 50048
#define KDIM 128

// Scratch (no cudaMalloc allowed) — two ping-pong node-feature buffers + degree/scale arrays.
__device__ float g_bufA[NODE_CAP * KDIM];
__device__ float g_bufB[NODE_CAP * KDIM];
__device__ int   g_degO[NODE_CAP];
__device__ int   g_degI[NODE_CAP];
__device__ float g_sO[NODE_CAP];
__device__ float g_sI[NODE_CAP];

// ---------------------------------------------------------------------------
// Degree count: int atomics, spread across 50000 counters.
// ---------------------------------------------------------------------------
__global__ void deg_kernel(const int* __restrict__ src, const int* __restrict__ dst, int E) {
    int i = blockIdx.x * blockDim.x + threadIdx.x;
    if (i < E) {
        atomicAdd(&g_degO[src[i]], 1);
        atomicAdd(&g_degI[dst[i]], 1);
    }
}

__global__ void scale_kernel(int n) {
    int i = blockIdx.x * blockDim.x + threadIdx.x;
    if (i < n) {
        g_sO[i] = rsqrtf((float)max(g_degO[i], 1));
        g_sI[i] = rsqrtf((float)max(g_degI[i], 1));
    }
}

// ---------------------------------------------------------------------------
// Scatter: one warp per edge. 32 lanes x float4 = 128 floats per row.
// Gather is a coalesced 512B read (L2-resident), scatter is red.global.add.v4.f32.
// ---------------------------------------------------------------------------
__global__ void scatter_kernel(const float4* __restrict__ H, float4* __restrict__ Out,
                               const int* __restrict__ src, const int* __restrict__ dst,
                               int E) {
    int gt = blockIdx.x * blockDim.x + threadIdx.x;
    int w = gt >> 5;
    int lane = gt & 31;
    if (w >= E) return;
    int s = __ldg(&src[w]);
    int d = __ldg(&dst[w]);
    float4 v = __ldg(&H[s * 32 + lane]);
    // result unused -> nvcc emits red.global (no return trip); float4 overload is sm_90+.
    atomicAdd(&Out[d * 32 + lane], v);
}

// ---------------------------------------------------------------------------
// Fused GEMM: C[M,N] = f(A[M,128]) @ W[128,N] (+ bias_out)
//   MODE 0: a = A[r][k] * s_out[r]                                  (layer1 in)
//   MODE 1: a = max(A[r][k]*s_in[r] + bias_in[k], 0) * s_out[r]     (layer1 epi + layer2 in)
//   MODE 2: a = A[r][k]*s_in[r] + bias_in[k];  out += bias_out[c]   (layer2 epi + final)
// BM=64 rows/block, 256 threads. W (K*N) and A-tile (64*K) staged in dynamic smem.
// ---------------------------------------------------------------------------
template <int N, int MODE>
__global__ void gemm_kernel(const float* __restrict__ A_src, const float* __restrict__ W,
                            const float* __restrict__ bias_in, const float* __restrict__ bias_out,
                            float* __restrict__ Out, int M) {
    constexpr int BM = 64;
    extern __shared__ float smem[];
    float* Ws = smem;            // K * N
    float* As = smem + KDIM * N; // BM * K

    int tid = threadIdx.x;
    int m0 = blockIdx.x * BM;

    // Stage W: coalesced float4 loads
    for (int i = tid * 4; i < KDIM * N; i += 256 * 4) {
        *(float4*)&Ws[i] = *(const float4*)&W[i];
    }

    // Stage A tile with fused prologue transform
    for (int i = tid; i < BM * KDIM / 4; i += 256) {
        int r = i >> 5;            // row within tile (32 float4 per row)
        int kc = (i & 31) * 4;     // k column
        int gr = m0 + r;
        float4 v = make_float4(0.f, 0.f, 0.f, 0.f);
        if (gr < M) {
            v = *(const float4*)&A_src[gr * KDIM + kc];
            if (MODE == 0) {
                float so = g_sO[gr];
                v.x *= so; v.y *= so; v.z *= so; v.w *= so;
            } else if (MODE == 1) {
                float si = g_sI[gr], so = g_sO[gr];
                float4 b = *(const float4*)&bias_in[kc];
                v.x = fmaxf(v.x * si + b.x, 0.f) * so;
                v.y = fmaxf(v.y * si + b.y, 0.f) * so;
                v.z = fmaxf(v.z * si + b.z, 0.f) * so;
                v.w = fmaxf(v.w * si + b.w, 0.f) * so;
            } else { // MODE 2
                float si = g_sI[gr];
                float4 b = *(const float4*)&bias_in[kc];
                v.x = v.x * si + b.x;
                v.y = v.y * si + b.y;
                v.z = v.z * si + b.z;
                v.w = v.w * si + b.w;
            }
        }
        *(float4*)&As[r * KDIM + kc] = v;
    }
    __syncthreads();

    // Register tiling: CT col-threads x RT row-threads; each thread RPT rows x 4 cols.
    constexpr int CT = N / 4;        // 32 (N=128) or 16 (N=64)
    constexpr int RT = 256 / CT;     // 8 or 16
    constexpr int RPT = BM / RT;     // 8 or 4
    int ct = tid % CT;
    int rt = tid / CT;
    int c0 = ct * 4;
    int r0 = rt * RPT;

    float4 acc[RPT];
#pragma unroll
    for (int i = 0; i < RPT; i++) acc[i] = make_float4(0.f, 0.f, 0.f, 0.f);

#pragma unroll 4
    for (int k = 0; k < KDIM; k++) {
        float4 b = *(const float4*)&Ws[k * N + c0];   // conflict-free LDS.128
#pragma unroll
        for (int i = 0; i < RPT; i++) {
            float a = As[(r0 + i) * KDIM + k];        // warp-broadcast LDS
            acc[i].x += a * b.x;
            acc[i].y += a * b.y;
            acc[i].z += a * b.z;
            acc[i].w += a * b.w;
        }
    }

#pragma unroll
    for (int i = 0; i < RPT; i++) {
        int gr = m0 + r0 + i;
        if (gr < M) {
            float4 o = acc[i];
            if (MODE == 2) {
                float4 bo = *(const float4*)&bias_out[c0];
                o.x += bo.x; o.y += bo.y; o.z += bo.z; o.w += bo.w;
            }
            *(float4*)&Out[gr * N + c0] = o;
        }
    }
}

// ---------------------------------------------------------------------------
extern "C" void kernel_launch(void* const* d_in, const int* in_sizes, int n_in,
                              void* d_out, int out_size) {
    const float* X  = (const float*)d_in[0];
    const int* src  = (const int*)d_in[1];
    const int* dst  = (const int*)d_in[2];
    const float* W1 = (const float*)d_in[3];
    const float* b1 = (const float*)d_in[4];
    const float* W2 = (const float*)d_in[5];
    const float* b2 = (const float*)d_in[6];
    const float* Wf = (const float*)d_in[7];
    const float* bf = (const float*)d_in[8];
    float* out = (float*)d_out;

    int n = in_sizes[0] / KDIM;   // 50000
    int E = in_sizes[1];          // 1600000

    void *pA_, *pB_, *pDO_, *pDI_;
    cudaGetSymbolAddress(&pA_, g_bufA);
    cudaGetSymbolAddress(&pB_, g_bufB);
    cudaGetSymbolAddress(&pDO_, g_degO);
    cudaGetSymbolAddress(&pDI_, g_degI);
    float* pA = (float*)pA_;
    float* pB = (float*)pB_;

    // Dynamic smem opt-in (>48KB)
    static_assert(KDIM == 128, "");
    const int smem128 = (KDIM * 128 + 64 * KDIM) * sizeof(float); // 96KB
    const int smem64  = (KDIM * 64  + 64 * KDIM) * sizeof(float); // 64KB
    cudaFuncSetAttribute(gemm_kernel<128, 0>, cudaFuncAttributeMaxDynamicSharedMemorySize, smem128);
    cudaFuncSetAttribute(gemm_kernel<128, 1>, cudaFuncAttributeMaxDynamicSharedMemorySize, smem128);
    cudaFuncSetAttribute(gemm_kernel<64, 2>,  cudaFuncAttributeMaxDynamicSharedMemorySize, smem64);

    int gemm_blocks = (n + 63) / 64;
    int scat_blocks = (E * 32 + 255) / 256;

    // 1. degrees -> scales
    cudaMemsetAsync(pDO_, 0, n * sizeof(int));
    cudaMemsetAsync(pDI_, 0, n * sizeof(int));
    deg_kernel<<<(E + 255) / 256, 256>>>(src, dst, E);
    scale_kernel<<<(n + 255) / 256, 256>>>(n);

    // 2. layer 1 GEMM: A = (X * s_out) @ W1
    gemm_kernel<128, 0><<<gemm_blocks, 256, smem128>>>(X, W1, nullptr, nullptr, pA, n);

    // 3. aggregate: B[dst] += A[src]
    cudaMemsetAsync(pB, 0, (size_t)n * KDIM * sizeof(float));
    scatter_kernel<<<scat_blocks, 256>>>((const float4*)pA, (float4*)pB, src, dst, E);

    // 4. layer 2 GEMM: A = (relu(B*s_in + b1) * s_out) @ W2
    gemm_kernel<128, 1><<<gemm_blocks, 256, smem128>>>(pB, W2, b1, nullptr, pA, n);

    // 5. aggregate: B[dst] += A[src]
    cudaMemsetAsync(pB, 0, (size_t)n * KDIM * sizeof(float));
    scatter_kernel<<<scat_blocks, 256>>>((const float4*)pA, (float4*)pB, src, dst, E);

    // 6. final: out = (B*s_in + b2) @ Wf + bf
    gemm_kernel<64, 2><<<gemm_blocks, 256, smem64>>>(pB, Wf, b2, bf, out, n);
}

// round 4
// speedup vs baseline: 1.3497x; 1.3497x over previous
#include <cuda_runtime.h>
#include <cuda_bf16.h>

// Problem constants (fixed by dataset): N=50000 nodes, E=1.6M edges, K=128 feat dim.
#define NODE_CAP 50048
#define EDGE_CAP 1700000
#define KDIM 128

// Scratch (no cudaMalloc allowed).
__device__ float g_bufA[NODE_CAP * KDIM];
__device__ float g_bufB[NODE_CAP * KDIM];
__device__ int   g_degO[NODE_CAP];
__device__ int   g_degI[NODE_CAP];
__device__ float g_sO[NODE_CAP];
__device__ float g_sI[NODE_CAP];
__device__ int   g_rowptr[NODE_CAP + 1];
__device__ int   g_cursor[NODE_CAP];
__device__ int   g_csr[EDGE_CAP];        // src indices grouped by dst

// ---------------------------------------------------------------------------
// Degree count: int atomics, spread across 50000 counters.
// ---------------------------------------------------------------------------
__global__ void deg_kernel(const int* __restrict__ src, const int* __restrict__ dst, int E) {
    int i = blockIdx.x * blockDim.x + threadIdx.x;
    if (i < E) {
        atomicAdd(&g_degO[src[i]], 1);
        atomicAdd(&g_degI[dst[i]], 1);
    }
}

__global__ void scale_kernel(int n) {
    int i = blockIdx.x * blockDim.x + threadIdx.x;
    if (i < n) {
        g_sO[i] = rsqrtf((float)max(g_degO[i], 1));
        g_sI[i] = rsqrtf((float)max(g_degI[i], 1));
    }
}

// ---------------------------------------------------------------------------
// Single-block prefix scan over deg_in -> row_ptr (exclusive) + cursor copy.
// 1024 threads, each owns a contiguous chunk; Hillis-Steele over partials.
// ---------------------------------------------------------------------------
__global__ void scan_kernel(int n) {
    __shared__ int part[1024];
    int tid = threadIdx.x;
    int CH = (n + 1023) / 1024;
    int beg = tid * CH;
    int sum = 0;
    for (int i = 0; i < CH; i++) {
        int idx = beg + i;
        if (idx < n) sum += g_degI[idx];
    }
    part[tid] = sum;
    __syncthreads();
    for (int off = 1; off < 1024; off <<= 1) {
        int v = (tid >= off) ? part[tid - off] : 0;
        __syncthreads();
        part[tid] += v;
        __syncthreads();
    }
    int run = (tid == 0) ? 0 : part[tid - 1];   // exclusive prefix of my chunk
    for (int i = 0; i < CH; i++) {
        int idx = beg + i;
        if (idx < n) {
            g_rowptr[idx] = run;
            g_cursor[idx] = run;
            run += g_degI[idx];
        }
    }
    if (tid == 1023) g_rowptr[n] = part[1023];  // total edge count
}

// Fill CSR: pos = cursor[dst]++ ; csr[pos] = src
__global__ void fill_kernel(const int* __restrict__ src, const int* __restrict__ dst, int E) {
    int i = blockIdx.x * blockDim.x + threadIdx.x;
    if (i < E) {
        int pos = atomicAdd(&g_cursor[dst[i]], 1);
        g_csr[pos] = src[i];
    }
}

// ---------------------------------------------------------------------------
// Pull-style aggregation: one warp per dst node. Lane l owns float4 column
// chunk l. Batch 32 edge indices per lane-load, broadcast via shfl, gather
// rows from L2, accumulate in registers, one plain STG.128 at the end.
// Traffic: E*512B reads + N*512B writes (no atomics).
// ---------------------------------------------------------------------------
__global__ void gather_kernel(const float4* __restrict__ H, float4* __restrict__ Out, int n) {
    int gt = blockIdx.x * blockDim.x + threadIdx.x;
    int w = gt >> 5;
    int l = gt & 31;
    if (w >= n) return;
    int beg = g_rowptr[w];
    int end = g_rowptr[w + 1];
    float4 a0 = make_float4(0.f, 0.f, 0.f, 0.f);
    float4 a1 = make_float4(0.f, 0.f, 0.f, 0.f);
    for (int base = beg; base < end; base += 32) {
        int e = base + l;
        int myidx = (e < end) ? __ldg(&g_csr[e]) : 0;
        int cnt = min(32, end - base);
        int j = 0;
        for (; j + 1 < cnt; j += 2) {
            int s0 = __shfl_sync(0xffffffffu, myidx, j);
            int s1 = __shfl_sync(0xffffffffu, myidx, j + 1);
            float4 v0 = __ldg(&H[s0 * 32 + l]);
            float4 v1 = __ldg(&H[s1 * 32 + l]);
            a0.x += v0.x; a0.y += v0.y; a0.z += v0.z; a0.w += v0.w;
            a1.x += v1.x; a1.y += v1.y; a1.z += v1.z; a1.w += v1.w;
        }
        if (j < cnt) {
            int s0 = __shfl_sync(0xffffffffu, myidx, j);
            float4 v0 = __ldg(&H[s0 * 32 + l]);
            a0.x += v0.x; a0.y += v0.y; a0.z += v0.z; a0.w += v0.w;
        }
    }
    float4 o = make_float4(a0.x + a1.x, a0.y + a1.y, a0.z + a1.z, a0.w + a1.w);
    Out[w * 32 + l] = o;
}

// ---------------------------------------------------------------------------
// Fused GEMM: C[M,N] = f(A[M,128]) @ W[128,N] (+ bias_out)
//   MODE 0: a = A[r][k] * s_out[r]
//   MODE 1: a = max(A[r][k]*s_in[r] + bias_in[k], 0) * s_out[r]
//   MODE 2: a = A[r][k]*s_in[r] + bias_in[k];  out += bias_out[c]
// ---------------------------------------------------------------------------
template <int N, int MODE>
__global__ void gemm_kernel(const float* __restrict__ A_src, const float* __restrict__ W,
                            const float* __restrict__ bias_in, const float* __restrict__ bias_out,
                            float* __restrict__ Out, int M) {
    constexpr int BM = 64;
    extern __shared__ float smem[];
    float* Ws = smem;            // K * N
    float* As = smem + KDIM * N; // BM * K

    int tid = threadIdx.x;
    int m0 = blockIdx.x * BM;

    for (int i = tid * 4; i < KDIM * N; i += 256 * 4) {
        *(float4*)&Ws[i] = *(const float4*)&W[i];
    }

    for (int i = tid; i < BM * KDIM / 4; i += 256) {
        int r = i >> 5;
        int kc = (i & 31) * 4;
        int gr = m0 + r;
        float4 v = make_float4(0.f, 0.f, 0.f, 0.f);
        if (gr < M) {
            v = *(const float4*)&A_src[gr * KDIM + kc];
            if (MODE == 0) {
                float so = g_sO[gr];
                v.x *= so; v.y *= so; v.z *= so; v.w *= so;
            } else if (MODE == 1) {
                float si = g_sI[gr], so = g_sO[gr];
                float4 b = *(const float4*)&bias_in[kc];
                v.x = fmaxf(v.x * si + b.x, 0.f) * so;
                v.y = fmaxf(v.y * si + b.y, 0.f) * so;
                v.z = fmaxf(v.z * si + b.z, 0.f) * so;
                v.w = fmaxf(v.w * si + b.w, 0.f) * so;
            } else {
                float si = g_sI[gr];
                float4 b = *(const float4*)&bias_in[kc];
                v.x = v.x * si + b.x;
                v.y = v.y * si + b.y;
                v.z = v.z * si + b.z;
                v.w = v.w * si + b.w;
            }
        }
        *(float4*)&As[r * KDIM + kc] = v;
    }
    __syncthreads();

    constexpr int CT = N / 4;
    constexpr int RT = 256 / CT;
    constexpr int RPT = BM / RT;
    int ct = tid % CT;
    int rt = tid / CT;
    int c0 = ct * 4;
    int r0 = rt * RPT;

    float4 acc[RPT];
#pragma unroll
    for (int i = 0; i < RPT; i++) acc[i] = make_float4(0.f, 0.f, 0.f, 0.f);

#pragma unroll 4
    for (int k = 0; k < KDIM; k++) {
        float4 b = *(const float4*)&Ws[k * N + c0];
#pragma unroll
        for (int i = 0; i < RPT; i++) {
            float a = As[(r0 + i) * KDIM + k];
            acc[i].x += a * b.x;
            acc[i].y += a * b.y;
            acc[i].z += a * b.z;
            acc[i].w += a * b.w;
        }
    }

#pragma unroll
    for (int i = 0; i < RPT; i++) {
        int gr = m0 + r0 + i;
        if (gr < M) {
            float4 o = acc[i];
            if (MODE == 2) {
                float4 bo = *(const float4*)&bias_out[c0];
                o.x += bo.x; o.y += bo.y; o.z += bo.z; o.w += bo.w;
            }
            *(float4*)&Out[gr * N + c0] = o;
        }
    }
}

// ---------------------------------------------------------------------------
extern "C" void kernel_launch(void* const* d_in, const int* in_sizes, int n_in,
                              void* d_out, int out_size) {
    const float* X  = (const float*)d_in[0];
    const int* src  = (const int*)d_in[1];
    const int* dst  = (const int*)d_in[2];
    const float* W1 = (const float*)d_in[3];
    const float* b1 = (const float*)d_in[4];
    const float* W2 = (const float*)d_in[5];
    const float* b2 = (const float*)d_in[6];
    const float* Wf = (const float*)d_in[7];
    const float* bf = (const float*)d_in[8];
    float* out = (float*)d_out;

    int n = in_sizes[0] / KDIM;   // 50000
    int E = in_sizes[1];          // 1600000

    void *pA_, *pB_, *pDO_, *pDI_;
    cudaGetSymbolAddress(&pA_, g_bufA);
    cudaGetSymbolAddress(&pB_, g_bufB);
    cudaGetSymbolAddress(&pDO_, g_degO);
    cudaGetSymbolAddress(&pDI_, g_degI);
    float* pA = (float*)pA_;
    float* pB = (float*)pB_;

    const int smem128 = (KDIM * 128 + 64 * KDIM) * sizeof(float); // 96KB
    const int smem64  = (KDIM * 64  + 64 * KDIM) * sizeof(float); // 64KB
    cudaFuncSetAttribute(gemm_kernel<128, 0>, cudaFuncAttributeMaxDynamicSharedMemorySize, smem128);
    cudaFuncSetAttribute(gemm_kernel<128, 1>, cudaFuncAttributeMaxDynamicSharedMemorySize, smem128);
    cudaFuncSetAttribute(gemm_kernel<64, 2>,  cudaFuncAttributeMaxDynamicSharedMemorySize, smem64);

    int gemm_blocks = (n + 63) / 64;
    int agg_blocks  = (n * 32 + 255) / 256;

    // 1. degrees
    cudaMemsetAsync(pDO_, 0, n * sizeof(int));
    cudaMemsetAsync(pDI_, 0, n * sizeof(int));
    deg_kernel<<<(E + 255) / 256, 256>>>(src, dst, E);

    // 2. CSR build (by dst) + scales
    scan_kernel<<<1, 1024>>>(n);
    fill_kernel<<<(E + 255) / 256, 256>>>(src, dst, E);
    scale_kernel<<<(n + 255) / 256, 256>>>(n);

    // 3. layer 1 GEMM: A = (X * s_out) @ W1
    gemm_kernel<128, 0><<<gemm_blocks, 256, smem128>>>(X, W1, nullptr, nullptr, pA, n);

    // 4. aggregate (pull): B[d] = sum_{s in N_in(d)} A[s]
    gather_kernel<<<agg_blocks, 256>>>((const float4*)pA, (float4*)pB, n);

    // 5. layer 2 GEMM: A = (relu(B*s_in + b1) * s_out) @ W2
    gemm_kernel<128, 1><<<gemm_blocks, 256, smem128>>>(pB, W2, b1, nullptr, pA, n);

    // 6. aggregate (pull)
    gather_kernel<<<agg_blocks, 256>>>((const float4*)pA, (float4*)pB, n);

    // 7. final: out = (B*s_in + b2) @ Wf + bf
    gemm_kernel<64, 2><<<gemm_blocks, 256, smem64>>>(pB, Wf, b2, bf, out, n);
}

// round 5
// speedup vs baseline: 1.6365x; 1.2125x over previous
#include <cuda_runtime.h>
#include <cuda_fp16.h>

// Problem constants (fixed by dataset): N=50000 nodes, E=1.6M edges, K=128 feat dim.
#define NODE_CAP 50048
#define EDGE_CAP 1700000
#define KDIM 128

// Scratch (no cudaMalloc allowed).
__device__ __align__(16) float  g_bufA[NODE_CAP * 64];    // gathered layer-2 (64-dim fp32)
__device__ __align__(16) float  g_bufB[NODE_CAP * KDIM];  // gathered layer-1 (128-dim fp32)
__device__ __align__(16) __half g_h1[NODE_CAP * KDIM];    // layer-1 pre-agg features (fp16)
__device__ __align__(16) __half g_h2[NODE_CAP * 64];      // layer-2 pre-agg features (fp16)
__device__ __align__(16) float  g_W2f[KDIM * 64];         // W2 @ Wf
__device__ __align__(16) float  g_c2[64];                 // b2 @ Wf + bf
__device__ int   g_degO[NODE_CAP];
__device__ int   g_degI[NODE_CAP];
__device__ float g_sO[NODE_CAP];
__device__ float g_sI[NODE_CAP];
__device__ int   g_rowptr[NODE_CAP + 1];
__device__ int   g_cursor[NODE_CAP];
__device__ int   g_csr[EDGE_CAP];        // src indices grouped by dst

// ---------------------------------------------------------------------------
// Degree count
// ---------------------------------------------------------------------------
__global__ void deg_kernel(const int* __restrict__ src, const int* __restrict__ dst, int E) {
    int i = blockIdx.x * blockDim.x + threadIdx.x;
    if (i < E) {
        atomicAdd(&g_degO[src[i]], 1);
        atomicAdd(&g_degI[dst[i]], 1);
    }
}

__global__ void scale_kernel(int n) {
    int i = blockIdx.x * blockDim.x + threadIdx.x;
    if (i < n) {
        g_sO[i] = rsqrtf((float)max(g_degO[i], 1));
        g_sI[i] = rsqrtf((float)max(g_degI[i], 1));
    }
}

// ---------------------------------------------------------------------------
// Single-block prefix scan over deg_in -> row_ptr (exclusive) + cursor copy.
// ---------------------------------------------------------------------------
__global__ void scan_kernel(int n) {
    __shared__ int part[1024];
    int tid = threadIdx.x;
    int CH = (n + 1023) / 1024;
    int beg = tid * CH;
    int sum = 0;
    for (int i = 0; i < CH; i++) {
        int idx = beg + i;
        if (idx < n) sum += g_degI[idx];
    }
    part[tid] = sum;
    __syncthreads();
    for (int off = 1; off < 1024; off <<= 1) {
        int v = (tid >= off) ? part[tid - off] : 0;
        __syncthreads();
        part[tid] += v;
        __syncthreads();
    }
    int run = (tid == 0) ? 0 : part[tid - 1];
    for (int i = 0; i < CH; i++) {
        int idx = beg + i;
        if (idx < n) {
            g_rowptr[idx] = run;
            g_cursor[idx] = run;
            run += g_degI[idx];
        }
    }
    if (tid == 1023) g_rowptr[n] = part[1023];
}

__global__ void fill_kernel(const int* __restrict__ src, const int* __restrict__ dst, int E) {
    int i = blockIdx.x * blockDim.x + threadIdx.x;
    if (i < E) {
        int pos = atomicAdd(&g_cursor[dst[i]], 1);
        g_csr[pos] = src[i];
    }
}

// ---------------------------------------------------------------------------
// Weight-fold precompute: W2f = W2 @ Wf  (128x64), c2 = b2 @ Wf + bf (64)
// ---------------------------------------------------------------------------
__global__ void prep_w_kernel(const float* __restrict__ W2, const float* __restrict__ Wf,
                              const float* __restrict__ b2, const float* __restrict__ bf) {
    int idx = blockIdx.x * blockDim.x + threadIdx.x;
    if (idx < KDIM * 64) {
        int i = idx >> 6;
        int j = idx & 63;
        float s = 0.f;
#pragma unroll 8
        for (int k = 0; k < KDIM; k++)
            s += __ldg(&W2[i * KDIM + k]) * __ldg(&Wf[k * 64 + j]);
        g_W2f[idx] = s;
    }
    if (blockIdx.x == 0 && threadIdx.x < 64) {
        int j = threadIdx.x;
        float s = __ldg(&bf[j]);
#pragma unroll 8
        for (int k = 0; k < KDIM; k++)
            s += __ldg(&b2[k]) * __ldg(&Wf[k * 64 + j]);
        g_c2[j] = s;
    }
}

// ---------------------------------------------------------------------------
// Pull aggregation, fp16 input, 128-dim rows. Warp per dst node; lane l owns
// halfs [4l, 4l+4) (one uint2 = 8B). Accumulate fp32, store float4.
// ---------------------------------------------------------------------------
__global__ void gather128h_kernel(const uint2* __restrict__ H, float4* __restrict__ Out, int n) {
    int gt = blockIdx.x * blockDim.x + threadIdx.x;
    int w = gt >> 5;
    int l = gt & 31;
    if (w >= n) return;
    int beg = g_rowptr[w];
    int end = g_rowptr[w + 1];
    float4 acc = make_float4(0.f, 0.f, 0.f, 0.f);
    for (int base = beg; base < end; base += 32) {
        int e = base + l;
        int myidx = (e < end) ? __ldg(&g_csr[e]) : 0;
        int cnt = min(32, end - base);
        for (int j = 0; j < cnt; j++) {
            int s = __shfl_sync(0xffffffffu, myidx, j);
            uint2 q = __ldg(&H[s * 32 + l]);
            __half2 p0 = *(__half2*)&q.x;
            __half2 p1 = *(__half2*)&q.y;
            float2 f0 = __half22float2(p0);
            float2 f1 = __half22float2(p1);
            acc.x += f0.x; acc.y += f0.y; acc.z += f1.x; acc.w += f1.y;
        }
    }
    Out[w * 32 + l] = acc;
}

// ---------------------------------------------------------------------------
// Pull aggregation, fp16 input, 64-dim rows. Lane l owns halfs [2l, 2l+2).
// ---------------------------------------------------------------------------
__global__ void gather64h_kernel(const __half2* __restrict__ H, float2* __restrict__ Out, int n) {
    int gt = blockIdx.x * blockDim.x + threadIdx.x;
    int w = gt >> 5;
    int l = gt & 31;
    if (w >= n) return;
    int beg = g_rowptr[w];
    int end = g_rowptr[w + 1];
    float2 acc = make_float2(0.f, 0.f);
    for (int base = beg; base < end; base += 32) {
        int e = base + l;
        int myidx = (e < end) ? __ldg(&g_csr[e]) : 0;
        int cnt = min(32, end - base);
        for (int j = 0; j < cnt; j++) {
            int s = __shfl_sync(0xffffffffu, myidx, j);
            float2 f = __half22float2(__ldg(&H[s * 32 + l]));
            acc.x += f.x; acc.y += f.y;
        }
    }
    Out[w * 32 + l] = acc;
}

// ---------------------------------------------------------------------------
// Fused GEMM: Ch[M,N] = f(A[M,128]) @ W[128,N], output fp16.
//   MODE 0: a = A[r][k] * s_out[r]
//   MODE 1: a = max(A[r][k]*s_in[r] + bias_in[k], 0) * s_out[r]
// ---------------------------------------------------------------------------
template <int N, int MODE>
__global__ void gemm_kernel(const float* __restrict__ A_src, const float* __restrict__ W,
                            const float* __restrict__ bias_in,
                            __half* __restrict__ Outh, int M) {
    constexpr int BM = 64;
    extern __shared__ float smem[];
    float* Ws = smem;            // K * N
    float* As = smem + KDIM * N; // BM * K

    int tid = threadIdx.x;
    int m0 = blockIdx.x * BM;

    for (int i = tid * 4; i < KDIM * N; i += 256 * 4) {
        *(float4*)&Ws[i] = *(const float4*)&W[i];
    }

    for (int i = tid; i < BM * KDIM / 4; i += 256) {
        int r = i >> 5;
        int kc = (i & 31) * 4;
        int gr = m0 + r;
        float4 v = make_float4(0.f, 0.f, 0.f, 0.f);
        if (gr < M) {
            v = *(const float4*)&A_src[gr * KDIM + kc];
            if (MODE == 0) {
                float so = g_sO[gr];
                v.x *= so; v.y *= so; v.z *= so; v.w *= so;
            } else {
                float si = g_sI[gr], so = g_sO[gr];
                float4 b = *(const float4*)&bias_in[kc];
                v.x = fmaxf(v.x * si + b.x, 0.f) * so;
                v.y = fmaxf(v.y * si + b.y, 0.f) * so;
                v.z = fmaxf(v.z * si + b.z, 0.f) * so;
                v.w = fmaxf(v.w * si + b.w, 0.f) * so;
            }
        }
        *(float4*)&As[r * KDIM + kc] = v;
    }
    __syncthreads();

    constexpr int CT = N / 4;        // 32 (N=128) or 16 (N=64)
    constexpr int RT = 256 / CT;     // 8 or 16
    constexpr int RPT = BM / RT;     // 8 or 4
    int ct = tid % CT;
    int rt = tid / CT;
    int c0 = ct * 4;
    int r0 = rt * RPT;

    float4 acc[RPT];
#pragma unroll
    for (int i = 0; i < RPT; i++) acc[i] = make_float4(0.f, 0.f, 0.f, 0.f);

#pragma unroll 4
    for (int k = 0; k < KDIM; k++) {
        float4 b = *(const float4*)&Ws[k * N + c0];
#pragma unroll
        for (int i = 0; i < RPT; i++) {
            float a = As[(r0 + i) * KDIM + k];
            acc[i].x += a * b.x;
            acc[i].y += a * b.y;
            acc[i].z += a * b.z;
            acc[i].w += a * b.w;
        }
    }

#pragma unroll
    for (int i = 0; i < RPT; i++) {
        int gr = m0 + r0 + i;
        if (gr < M) {
            float4 o = acc[i];
            __half2 lo = __floats2half2_rn(o.x, o.y);
            __half2 hi = __floats2half2_rn(o.z, o.w);
            uint2 u;
            u.x = *(unsigned*)&lo;
            u.y = *(unsigned*)&hi;
            *(uint2*)&Outh[gr * N + c0] = u;
        }
    }
}

// ---------------------------------------------------------------------------
// Epilogue: out[r][c] = G[r][c] * sI[r] + c2[c]   (out is n x 64 fp32)
// ---------------------------------------------------------------------------
__global__ void epi_kernel(const float4* __restrict__ G, float4* __restrict__ Out, int n) {
    int i = blockIdx.x * blockDim.x + threadIdx.x;
    if (i >= n * 16) return;
    int r = i >> 4;
    int c = (i & 15) * 4;
    float si = g_sI[r];
    float4 g = G[i];
    float4 b = *(const float4*)&g_c2[c];
    float4 o;
    o.x = g.x * si + b.x;
    o.y = g.y * si + b.y;
    o.z = g.z * si + b.z;
    o.w = g.w * si + b.w;
    Out[i] = o;
}

// ---------------------------------------------------------------------------
extern "C" void kernel_launch(void* const* d_in, const int* in_sizes, int n_in,
                              void* d_out, int out_size) {
    const float* X  = (const float*)d_in[0];
    const int* src  = (const int*)d_in[1];
    const int* dst  = (const int*)d_in[2];
    const float* W1 = (const float*)d_in[3];
    const float* b1 = (const float*)d_in[4];
    const float* W2 = (const float*)d_in[5];
    const float* b2 = (const float*)d_in[6];
    const float* Wf = (const float*)d_in[7];
    const float* bf = (const float*)d_in[8];
    float* out = (float*)d_out;

    int n = in_sizes[0] / KDIM;   // 50000
    int E = in_sizes[1];          // 1600000

    void *pA_, *pB_, *pH1_, *pH2_, *pW2f_, *pDO_, *pDI_;
    cudaGetSymbolAddress(&pA_, g_bufA);
    cudaGetSymbolAddress(&pB_, g_bufB);
    cudaGetSymbolAddress(&pH1_, g_h1);
    cudaGetSymbolAddress(&pH2_, g_h2);
    cudaGetSymbolAddress(&pW2f_, g_W2f);
    cudaGetSymbolAddress(&pDO_, g_degO);
    cudaGetSymbolAddress(&pDI_, g_degI);

    const int smem128 = (KDIM * 128 + 64 * KDIM) * sizeof(float); // 96KB
    const int smem64  = (KDIM * 64  + 64 * KDIM) * sizeof(float); // 64KB
    cudaFuncSetAttribute(gemm_kernel<128, 0>, cudaFuncAttributeMaxDynamicSharedMemorySize, smem128);
    cudaFuncSetAttribute(gemm_kernel<64, 1>,  cudaFuncAttributeMaxDynamicSharedMemorySize, smem64);

    int gemm_blocks = (n + 63) / 64;
    int agg_blocks  = (n * 32 + 255) / 256;

    // 1. degrees -> CSR (by dst) + scales; fold Wf into W2.
    cudaMemsetAsync(pDO_, 0, n * sizeof(int));
    cudaMemsetAsync(pDI_, 0, n * sizeof(int));
    deg_kernel<<<(E + 255) / 256, 256>>>(src, dst, E);
    prep_w_kernel<<<(KDIM * 64 + 255) / 256, 256>>>(W2, Wf, b2, bf);
    scan_kernel<<<1, 1024>>>(n);
    fill_kernel<<<(E + 255) / 256, 256>>>(src, dst, E);
    scale_kernel<<<(n + 255) / 256, 256>>>(n);

    // 2. layer 1 GEMM: h1 (fp16) = (X * s_out) @ W1
    gemm_kernel<128, 0><<<gemm_blocks, 256, smem128>>>(X, W1, nullptr, (__half*)pH1_, n);

    // 3. aggregate (pull, fp16 in): B = agg(h1)
    gather128h_kernel<<<agg_blocks, 256>>>((const uint2*)pH1_, (float4*)pB_, n);

    // 4. layer 2 + final fold: h2 (fp16) = (relu(B*s_in + b1) * s_out) @ (W2@Wf)
    gemm_kernel<64, 1><<<gemm_blocks, 256, smem64>>>((const float*)pB_, (const float*)pW2f_,
                                                     b1, (__half*)pH2_, n);

    // 5. aggregate (pull, fp16 in, 64-dim): G = agg(h2)
    gather64h_kernel<<<agg_blocks, 256>>>((const __half2*)pH2_, (float2*)pA_, n);

    // 6. epilogue: out = G * s_in + (b2@Wf + bf)
    epi_kernel<<<(n * 16 + 255) / 256, 256>>>((const float4*)pA_, (float4*)out, n);
}